// round 16
// baseline (speedup 1.0000x reference)
#include <cuda_runtime.h>
#include <cuda_fp16.h>
#include <math.h>
#include <stdint.h>

#define BATCH 4
#define SEQ   4096
#define DIM   1024
#define HEADS 16
#define DHEAD 64
#define MROWS (BATCH*SEQ)                 // 16384
#define SCALE 0.5946035575013605f         // (sqrt(64))^(-0.25)

// ---------------- scratch ----------------------------------------------------
__device__ float g_ctx[BATCH * HEADS * DHEAD * DHEAD];
__device__ float g_qsum[BATCH * DIM];
__device__ float g_bqv[2 * DIM];
__device__ __half g_xh[(size_t)MROWS * DIM];     // x fp16 (A of QV gemm)
__device__ __half g_qh[(size_t)MROWS * DIM];     // softmaxed q fp16
__device__ __half g_vh[(size_t)MROWS * DIM];     // v fp16
__device__ __half g_wth[2u * DIM * DIM];         // [Wq^T;Wv^T] fp16
__device__ __half g_foldh[(size_t)BATCH * DIM * DIM];  // Wfold^T fp16 (per batch)

// ---------------- helpers ----------------------------------------------------
__device__ __forceinline__ uint32_t smem_u32(const void* p) {
    uint32_t a;
    asm("{ .reg .u64 t; cvta.to.shared.u64 t, %1; cvt.u32.u64 %0, t; }"
        : "=r"(a) : "l"(p));
    return a;
}
__device__ __forceinline__ void cp16(uint32_t dst, const void* src) {
    asm volatile("cp.async.cg.shared.global [%0], [%1], 16;" :: "r"(dst), "l"(src));
}
#define SWZ(x) ((x) ^ (((x) >> 3) & 0x70))

__device__ __forceinline__ void ldsm4(uint32_t addr, uint32_t& r0, uint32_t& r1,
                                      uint32_t& r2, uint32_t& r3) {
    asm volatile("ldmatrix.sync.aligned.m8n8.x4.shared.b16 {%0,%1,%2,%3}, [%4];"
                 : "=r"(r0), "=r"(r1), "=r"(r2), "=r"(r3) : "r"(addr));
}
__device__ __forceinline__ void mma16816(float* d, const uint32_t* a,
                                         const uint32_t* b) {
    asm volatile("mma.sync.aligned.m16n8k16.row.col.f32.f16.f16.f32 "
                 "{%0,%1,%2,%3}, {%4,%5,%6,%7}, {%8,%9}, {%0,%1,%2,%3};"
                 : "+f"(d[0]), "+f"(d[1]), "+f"(d[2]), "+f"(d[3])
                 : "r"(a[0]), "r"(a[1]), "r"(a[2]), "r"(a[3]),
                   "r"(b[0]), "r"(b[1]));
}

// ---------------- fused prep: to_half(x) + transpose Wq/Wv + init ------------
#define PREP_XBLK   16384
#define PREP_TBLK   (PREP_XBLK + 2048)
#define PREP_NBLK   (PREP_TBLK + 1024)
__global__ __launch_bounds__(256)
void prep(const float4* __restrict__ x,
          const float* __restrict__ Wq, const float* __restrict__ Wv,
          const float* __restrict__ bq, const float* __restrict__ bv)
{
    const int blk = blockIdx.x, tid = threadIdx.x;
    if (blk < PREP_XBLK) {
        int i = blk * 256 + tid;
        float4 v = x[i];
        __half2 a = __floats2half2_rn(v.x, v.y);
        __half2 b = __floats2half2_rn(v.z, v.w);
        ((uint2*)g_xh)[i] = make_uint2(*(uint32_t*)&a, *(uint32_t*)&b);
    } else if (blk < PREP_TBLK) {
        int t = blk - PREP_XBLK;
        const float* W = (t < 1024) ? Wq : Wv;
        __half* th = g_wth + (size_t)(t < 1024 ? 0 : 1) * DIM * DIM;
        int tile = t & 1023;
        int bx = (tile & 31) * 32, by = (tile >> 5) * 32;
        __shared__ float ts[32][33];
        int xI = tid & 31, y0 = tid >> 5;
#pragma unroll
        for (int j = 0; j < 32; j += 8)
            ts[y0 + j][xI] = W[(size_t)(by + y0 + j) * DIM + bx + xI];
        __syncthreads();
#pragma unroll
        for (int j = 0; j < 32; j += 8) {
            size_t o = (size_t)(bx + y0 + j) * DIM + by + xI;
            th[o] = __float2half_rn(ts[xI][y0 + j]);
        }
    } else {
        int i = (blk - PREP_TBLK) * 256 + tid;    // 0 .. 262,143
        if (i < DIM) g_bqv[i] = bq[i];
        else if (i < 2 * DIM) g_bqv[i] = bv[i - DIM];
        if (i < BATCH * DIM) g_qsum[i] = 0.f;
        g_ctx[i] = 0.f;
    }
}

// ---------------- single-pass fp16 mma.sync GEMM -----------------------------
// CTA 256x128, 512 thr, warp tile 32x64 (16 warps: 8m x 2n), K-tile 64, 4 stages.
#define NITER 16
#define STG_BYTES 49152   // 32KB A + 16KB B

__global__ __launch_bounds__(512, 1)
void gemm_mma(const __half* __restrict__ Ah, const __half* __restrict__ Bh0,
              const float* __restrict__ bias, float* __restrict__ Cout,
              __half* __restrict__ Qh, __half* __restrict__ Vh, int mode)
{
    extern __shared__ char smem_raw[];
    const uint32_t sb = (smem_u32(smem_raw) + 127) & ~127u;
    float* scr = (float*)smem_raw;
    const int tid = threadIdx.x, wid = tid >> 5, lane = tid & 31;
    const int bm = blockIdx.y * 256, bn = blockIdx.x * 128;
    const int wm = (wid >> 1) * 32;
    const int wn = (wid & 1) * 64;

    const __half* Bh = Bh0;
    if (mode == 1) Bh += (size_t)(blockIdx.y >> 4) * DIM * DIM;
    const bool isq = (mode == 0) && (bn < 1024);
    const int cbn = (mode == 0 && bn >= 1024) ? bn - 1024 : bn;

    const int arow = tid >> 1, aci = (tid & 1) * 4;
    const int brow = tid >> 2, bci = (tid & 3) * 2;

    auto load = [&](int it) {
        const int k0 = it << 6;
        const __half* A = Ah + (size_t)(bm + arow) * DIM + k0 + aci * 8;
        const __half* B = Bh + (size_t)(bn + brow) * DIM + k0 + bci * 8;
        const uint32_t base = sb + (uint32_t)(it & 3) * STG_BYTES;
#pragma unroll
        for (int i = 0; i < 4; i++)
            cp16(base + SWZ((uint32_t)(arow * 128 + (aci + i) * 16)), A + i * 8);
#pragma unroll
        for (int i = 0; i < 2; i++)
            cp16(base + 32768 + SWZ((uint32_t)(brow * 128 + (bci + i) * 16)), B + i * 8);
        asm volatile("cp.async.commit_group;" ::: "memory");
    };

    float acc[2][8][4];
#pragma unroll
    for (int mb = 0; mb < 2; mb++)
#pragma unroll
        for (int nb = 0; nb < 8; nb++)
#pragma unroll
            for (int j = 0; j < 4; j++) acc[mb][nb][j] = 0.f;

    load(0); load(1); load(2);

    const int la_row = lane & 15;
    const int la_kh = lane >> 4;
    const int lb_n = ((lane >> 4) << 3) + (lane & 7);
    const int lb_kh = (lane >> 3) & 1;

    for (int it = 0; it < NITER; it++) {
        asm volatile("cp.async.wait_group 2;" ::: "memory");
        __syncthreads();
        if (it + 3 < NITER) load(it + 3);
        else asm volatile("cp.async.commit_group;" ::: "memory");

        const uint32_t abase = sb + (uint32_t)(it & 3) * STG_BYTES;
        const uint32_t bbase = abase + 32768;
#pragma unroll
        for (int kk = 0; kk < 4; kk++) {
            uint32_t af[2][4];
#pragma unroll
            for (int mb = 0; mb < 2; mb++) {
                uint32_t off = (uint32_t)((wm + mb * 16 + la_row) * 128 +
                                          (kk * 16 + la_kh * 8) * 2);
                ldsm4(abase + SWZ(off), af[mb][0], af[mb][1], af[mb][2], af[mb][3]);
            }
            const uint32_t boff_n = (uint32_t)((wn + lb_n) * 128 +
                                               (kk * 16 + lb_kh * 8) * 2);
            uint32_t bf[8][2];
#pragma unroll
            for (int nb2 = 0; nb2 < 4; nb2++) {
                uint32_t r0, r1, r2, r3;
                ldsm4(bbase + SWZ(boff_n + (uint32_t)(nb2 * 16 * 128)), r0, r1, r2, r3);
                bf[nb2 * 2][0] = r0;     bf[nb2 * 2][1] = r1;
                bf[nb2 * 2 + 1][0] = r2; bf[nb2 * 2 + 1][1] = r3;
            }
#pragma unroll
            for (int mb = 0; mb < 2; mb++)
#pragma unroll
                for (int nb = 0; nb < 8; nb++)
                    mma16816(acc[mb][nb], af[mb], bf[nb]);
        }
    }

    // ---- epilogue ----
    __syncthreads();
    if (tid < 128) scr[tid] = 0.f;
    __syncthreads();

    const int quad = lane >> 2, qt = lane & 3;
    float bia[8][2];
#pragma unroll
    for (int nb = 0; nb < 8; nb++) {
        int col = bn + wn + nb * 8 + qt * 2;
        bia[nb][0] = bias[col];
        bia[nb][1] = bias[col + 1];
    }
#pragma unroll
    for (int mb = 0; mb < 2; mb++) {
#pragma unroll
        for (int h = 0; h < 2; h++) {
            float v[16];
#pragma unroll
            for (int nb = 0; nb < 8; nb++) {
                v[nb * 2]     = acc[mb][nb][h * 2]     + bia[nb][0];
                v[nb * 2 + 1] = acc[mb][nb][h * 2 + 1] + bia[nb][1];
            }
            int row = bm + wm + mb * 16 + h * 8 + quad;
            if (mode == 1) {
                float* crow = Cout + (size_t)row * DIM + cbn + wn + qt * 2;
#pragma unroll
                for (int nb = 0; nb < 8; nb++)
                    *(float2*)&crow[nb * 8] = make_float2(v[nb * 2], v[nb * 2 + 1]);
            } else if (isq) {
                float m = v[0];
#pragma unroll
                for (int j = 1; j < 16; j++) m = fmaxf(m, v[j]);
                m = fmaxf(m, __shfl_xor_sync(0xffffffffu, m, 1));
                m = fmaxf(m, __shfl_xor_sync(0xffffffffu, m, 2));
                float s = 0.f;
#pragma unroll
                for (int j = 0; j < 16; j++) { v[j] = expf(v[j] - m); s += v[j]; }
                s += __shfl_xor_sync(0xffffffffu, s, 1);
                s += __shfl_xor_sync(0xffffffffu, s, 2);
                float inv = SCALE / s;
#pragma unroll
                for (int j = 0; j < 16; j++) v[j] *= inv;
                // column sums of exp(q); q in [0, SCALE] -> exp bounded, no max pass
                float es[16];
#pragma unroll
                for (int j = 0; j < 16; j++) es[j] = expf(v[j]);
#pragma unroll
                for (int off = 4; off < 32; off <<= 1)
#pragma unroll
                    for (int j = 0; j < 16; j++)
                        es[j] += __shfl_xor_sync(0xffffffffu, es[j], off);
                if (quad == 0) {
#pragma unroll
                    for (int j = 0; j < 16; j++)
                        atomicAdd(&scr[wn + (j >> 1) * 8 + qt * 2 + (j & 1)], es[j]);
                }
                __half* qrow = Qh + (size_t)row * DIM + cbn + wn + qt * 2;
#pragma unroll
                for (int nb = 0; nb < 8; nb++)
                    *(__half2*)&qrow[nb * 8] = __floats2half2_rn(v[nb * 2], v[nb * 2 + 1]);
            } else {
                __half* vrow = Vh + (size_t)row * DIM + cbn + wn + qt * 2;
#pragma unroll
                for (int nb = 0; nb < 8; nb++)
                    *(__half2*)&vrow[nb * 8] = __floats2half2_rn(v[nb * 2], v[nb * 2 + 1]);
            }
        }
    }
    if (isq) {
        __syncthreads();
        if (tid < 128) {
            int b = blockIdx.y >> 4;
            atomicAdd(&g_qsum[b * DIM + bn + tid], scr[tid]);
        }
    }
}

// ---------------- tensor-core ctx: ctx[b,h,d,e] = cinv[d]*sum_n exp(q)[n,d]*v[n,e]
__global__ __launch_bounds__(256)
void ctx_mma()
{
    __shared__ __align__(128) __half ks[64 * 64];
    __shared__ __align__(128) __half vs[64 * 64];
    const int tid = threadIdx.x, wid = tid >> 5, lane = tid & 31;
    const int bh = blockIdx.y, b = bh >> 4, h = bh & 15;
    const size_t nbase = (size_t)b * SEQ + blockIdx.x * 512;
    const __half* qb = g_qh + nbase * DIM + h * DHEAD;
    const __half* vb = g_vh + nbase * DIM + h * DHEAD;
    const uint32_t ksb = smem_u32(ks), vsb = smem_u32(vs);

    const int dslice = wid & 3;
    const int nh = wid >> 2;
    const int la_row = lane & 15;
    const int la_kh = lane >> 4;
    const int lb_n = ((lane >> 4) << 3) + (lane & 7);
    const int lb_kh = (lane >> 3) & 1;

    float acc[8][4];
#pragma unroll
    for (int nb = 0; nb < 8; nb++)
#pragma unroll
        for (int j = 0; j < 4; j++) acc[nb][j] = 0.f;

    const int r = tid >> 2;
    const int c0 = (tid & 3) * 16;

    for (int t = 0; t < 8; t++) {
        const __half* qrow = qb + (size_t)(t * 64 + r) * DIM;
        const __half* vrow = vb + (size_t)(t * 64 + r) * DIM;
        uint4 qa = *(const uint4*)(qrow + c0);
        uint4 qc = *(const uint4*)(qrow + c0 + 8);
        uint4 va = *(const uint4*)(vrow + c0);
        uint4 vc = *(const uint4*)(vrow + c0 + 8);
        __syncthreads();
        {
            const __half2* qp = (const __half2*)&qa;
#pragma unroll
            for (int j = 0; j < 4; j++) {
                __half2 e = h2exp(qp[j]);
                *(__half*)((char*)ks + SWZ((uint32_t)((c0 + 2*j) * 128 + r * 2))) =
                    __low2half(e);
                *(__half*)((char*)ks + SWZ((uint32_t)((c0 + 2*j + 1) * 128 + r * 2))) =
                    __high2half(e);
            }
            const __half2* qp2 = (const __half2*)&qc;
#pragma unroll
            for (int j = 0; j < 4; j++) {
                __half2 e = h2exp(qp2[j]);
                *(__half*)((char*)ks + SWZ((uint32_t)((c0 + 8 + 2*j) * 128 + r * 2))) =
                    __low2half(e);
                *(__half*)((char*)ks + SWZ((uint32_t)((c0 + 8 + 2*j + 1) * 128 + r * 2))) =
                    __high2half(e);
            }
            const __half* vp = (const __half*)&va;
#pragma unroll
            for (int j = 0; j < 8; j++)
                *(__half*)((char*)vs + SWZ((uint32_t)((c0 + j) * 128 + r * 2))) = vp[j];
            const __half* vp2 = (const __half*)&vc;
#pragma unroll
            for (int j = 0; j < 8; j++)
                *(__half*)((char*)vs + SWZ((uint32_t)((c0 + 8 + j) * 128 + r * 2))) = vp2[j];
        }
        __syncthreads();

#pragma unroll
        for (int s = 0; s < 2; s++) {
            const int kk = nh * 2 + s;
            uint32_t af[4];
            {
                uint32_t off = (uint32_t)((dslice * 16 + la_row) * 128 +
                                          (kk * 16 + la_kh * 8) * 2);
                ldsm4(ksb + SWZ(off), af[0], af[1], af[2], af[3]);
            }
            uint32_t bf[8][2];
#pragma unroll
            for (int eb = 0; eb < 4; eb++) {
                uint32_t off = (uint32_t)((eb * 16 + lb_n) * 128 +
                                          (kk * 16 + lb_kh * 8) * 2);
                uint32_t r0, r1, r2, r3;
                ldsm4(vsb + SWZ(off), r0, r1, r2, r3);
                bf[eb * 2][0] = r0;     bf[eb * 2][1] = r1;
                bf[eb * 2 + 1][0] = r2; bf[eb * 2 + 1][1] = r3;
            }
#pragma unroll
            for (int nb = 0; nb < 8; nb++)
                mma16816(acc[nb], af, bf[nb]);
        }
    }

    // reduce with inline cinv[d] = SCALE / qsum
    const int g = lane >> 2, t4 = lane & 3;
    const int d0 = dslice * 16 + g;
    const float ci0 = SCALE / g_qsum[b * DIM + h * DHEAD + d0];
    const float ci1 = SCALE / g_qsum[b * DIM + h * DHEAD + d0 + 8];
    float* cb = g_ctx + (size_t)bh * 4096;
#pragma unroll
    for (int nb = 0; nb < 8; nb++) {
        int e = nb * 8 + t4 * 2;
        atomicAdd(&cb[d0 * 64 + e],           acc[nb][0] * ci0);
        atomicAdd(&cb[d0 * 64 + e + 1],       acc[nb][1] * ci0);
        atomicAdd(&cb[(d0 + 8) * 64 + e],     acc[nb][2] * ci1);
        atomicAdd(&cb[(d0 + 8) * 64 + e + 1], acc[nb][3] * ci1);
    }
}

// ---------------- tensor-core fold: Wfold^T[b][jt+j][h*64+d] -----------------
__global__ __launch_bounds__(256)
void fold_mma(const float* __restrict__ Wo, __half* __restrict__ fh)
{
    __shared__ __align__(128) __half aw[128 * 64];  // [j][e] SWZ
    __shared__ __align__(128) __half cs[64 * 64];   // [d][e] SWZ
    const int tid = threadIdx.x, wid = tid >> 5, lane = tid & 31;
    const int bh = blockIdx.y, b = bh >> 4, h = bh & 15;
    const int jt = blockIdx.x * 128;
    const uint32_t awb = smem_u32(aw), csb = smem_u32(cs);

    // ctx -> cs fp16 (vectorized, conflict-free)
    const float* cb = g_ctx + (size_t)bh * 4096;
    for (int i = tid; i < 2048; i += 256) {
        int d = i >> 5, e2 = (i & 31) * 2;
        float2 f = *(const float2*)&cb[d * 64 + e2];
        *(__half2*)((char*)cs + SWZ((uint32_t)(d * 128 + e2 * 2))) =
            __floats2half2_rn(f.x, f.y);
    }
    // Wo -> aw transposed: each thread reads 2 e-rows for one j (both reads
    // coalesced over j) and writes one half2 -> half the smem stores of scalar.
    const float* wo = Wo + (size_t)(h * 64) * DIM + jt;
    for (int i = tid; i < 4096; i += 256) {
        int j = i & 127, e2 = (i >> 7) * 2;
        float w0 = wo[(size_t)e2 * DIM + j];
        float w1 = wo[(size_t)(e2 + 1) * DIM + j];
        *(__half2*)((char*)aw + SWZ((uint32_t)(j * 128 + e2 * 2))) =
            __floats2half2_rn(w0, w1);
    }
    __syncthreads();

    const int la_row = lane & 15, la_kh = lane >> 4;
    const int lb_n = ((lane >> 4) << 3) + (lane & 7);
    const int lb_kh = (lane >> 3) & 1;
    const int j0 = wid * 16;

    float acc[8][4];
#pragma unroll
    for (int nb = 0; nb < 8; nb++)
#pragma unroll
        for (int j = 0; j < 4; j++) acc[nb][j] = 0.f;

#pragma unroll
    for (int kk = 0; kk < 4; kk++) {
        uint32_t af[4];
        ldsm4(awb + SWZ((uint32_t)((j0 + la_row) * 128 + (kk * 16 + la_kh * 8) * 2)),
              af[0], af[1], af[2], af[3]);
        uint32_t bf[8][2];
#pragma unroll
        for (int nb2 = 0; nb2 < 4; nb2++) {
            uint32_t r0, r1, r2, r3;
            ldsm4(csb + SWZ((uint32_t)((nb2 * 16 + lb_n) * 128 +
                                       (kk * 16 + lb_kh * 8) * 2)), r0, r1, r2, r3);
            bf[nb2 * 2][0] = r0;     bf[nb2 * 2][1] = r1;
            bf[nb2 * 2 + 1][0] = r2; bf[nb2 * 2 + 1][1] = r3;
        }
#pragma unroll
        for (int nb = 0; nb < 8; nb++)
            mma16816(acc[nb], af, bf[nb]);
    }

    // store fp16: fh[(b*DIM + jt + j)*DIM + h*64 + d]
    const int quad = lane >> 2, qt = lane & 3;
#pragma unroll
    for (int h8 = 0; h8 < 2; h8++) {
        int j = j0 + h8 * 8 + quad;
        __half* frow = fh + ((size_t)(b * DIM) + jt + j) * DIM + h * 64 + qt * 2;
#pragma unroll
        for (int nb = 0; nb < 8; nb++)
            *(__half2*)&frow[nb * 8] =
                __floats2half2_rn(acc[nb][h8 * 2], acc[nb][h8 * 2 + 1]);
    }
}

// -----------------------------------------------------------------------------
extern "C" void kernel_launch(void* const* d_in, const int* in_sizes, int n_in,
                              void* d_out, int out_size)
{
    const float* x  = (const float*)d_in[0];
    const float* Wq = (const float*)d_in[1];
    const float* bq = (const float*)d_in[2];
    const float* Wv = (const float*)d_in[5];
    const float* bv = (const float*)d_in[6];
    const float* Wo = (const float*)d_in[7];
    const float* bo = (const float*)d_in[8];
    float* out = (float*)d_out;

    __half *xh, *qh, *vh, *wth, *foldh;
    float* bqv;
    cudaGetSymbolAddress((void**)&bqv, g_bqv);
    cudaGetSymbolAddress((void**)&xh, g_xh);
    cudaGetSymbolAddress((void**)&qh, g_qh);
    cudaGetSymbolAddress((void**)&vh, g_vh);
    cudaGetSymbolAddress((void**)&wth, g_wth);
    cudaGetSymbolAddress((void**)&foldh, g_foldh);

    const int SMEM = 4 * STG_BYTES + 256;   // ~192.25KB (cap 227KB)
    cudaFuncSetAttribute(gemm_mma, cudaFuncAttributeMaxDynamicSharedMemorySize, SMEM);

    prep<<<PREP_NBLK, 256>>>((const float4*)x, Wq, Wv, bq, bv);

    // fused QV GEMM: N = 2048, M-tiles of 256
    gemm_mma<<<dim3(2 * DIM / 128, MROWS / 256), 512, SMEM>>>(
        xh, wth, bqv, nullptr, qh, vh, 0);
    ctx_mma<<<dim3(8, BATCH * HEADS), 256>>>();
    fold_mma<<<dim3(DIM / 128, BATCH * HEADS), 256>>>(Wo, foldh);
    // O GEMM: out = qh @ Wfold[b]^T + bo
    gemm_mma<<<dim3(DIM / 128, MROWS / 256), 512, SMEM>>>(
        qh, foldh, bo, out, nullptr, nullptr, 1);
}

// round 17
// speedup vs baseline: 1.0147x; 1.0147x over previous
#include <cuda_runtime.h>
#include <cuda_fp16.h>
#include <math.h>
#include <stdint.h>

#define BATCH 4
#define SEQ   4096
#define DIM   1024
#define HEADS 16
#define DHEAD 64
#define MROWS (BATCH*SEQ)                 // 16384
#define SCALE 0.5946035575013605f         // (sqrt(64))^(-0.25)

// ---------------- scratch ----------------------------------------------------
__device__ float g_ctx[BATCH * HEADS * DHEAD * DHEAD];
__device__ float g_qsum[BATCH * DIM];
__device__ float g_bqv[2 * DIM];
__device__ __half g_xh[(size_t)MROWS * DIM];     // x fp16 (A of QV gemm)
__device__ __half g_qh[(size_t)MROWS * DIM];     // softmaxed q fp16
__device__ __half g_vh[(size_t)MROWS * DIM];     // v fp16
__device__ __half g_wth[2u * DIM * DIM];         // [Wq^T;Wv^T] fp16
__device__ __half g_foldh[(size_t)BATCH * DIM * DIM];  // Wfold^T fp16 (per batch)

// ---------------- helpers ----------------------------------------------------
__device__ __forceinline__ uint32_t smem_u32(const void* p) {
    uint32_t a;
    asm("{ .reg .u64 t; cvta.to.shared.u64 t, %1; cvt.u32.u64 %0, t; }"
        : "=r"(a) : "l"(p));
    return a;
}
__device__ __forceinline__ void cp16(uint32_t dst, const void* src) {
    asm volatile("cp.async.cg.shared.global [%0], [%1], 16;" :: "r"(dst), "l"(src));
}
#define SWZ(x) ((x) ^ (((x) >> 3) & 0x70))

__device__ __forceinline__ void ldsm4(uint32_t addr, uint32_t& r0, uint32_t& r1,
                                      uint32_t& r2, uint32_t& r3) {
    asm volatile("ldmatrix.sync.aligned.m8n8.x4.shared.b16 {%0,%1,%2,%3}, [%4];"
                 : "=r"(r0), "=r"(r1), "=r"(r2), "=r"(r3) : "r"(addr));
}
__device__ __forceinline__ void mma16816(float* d, const uint32_t* a,
                                         const uint32_t* b) {
    asm volatile("mma.sync.aligned.m16n8k16.row.col.f32.f16.f16.f32 "
                 "{%0,%1,%2,%3}, {%4,%5,%6,%7}, {%8,%9}, {%0,%1,%2,%3};"
                 : "+f"(d[0]), "+f"(d[1]), "+f"(d[2]), "+f"(d[3])
                 : "r"(a[0]), "r"(a[1]), "r"(a[2]), "r"(a[3]),
                   "r"(b[0]), "r"(b[1]));
}

// ---------------- fused prep: to_half(x) + transpose Wq/Wv + init ------------
#define PREP_XBLK   16384
#define PREP_TBLK   (PREP_XBLK + 2048)
#define PREP_NBLK   (PREP_TBLK + 1024)
__global__ __launch_bounds__(256)
void prep(const float4* __restrict__ x,
          const float* __restrict__ Wq, const float* __restrict__ Wv,
          const float* __restrict__ bq, const float* __restrict__ bv)
{
    const int blk = blockIdx.x, tid = threadIdx.x;
    if (blk < PREP_XBLK) {
        int i = blk * 256 + tid;
        float4 v = x[i];
        __half2 a = __floats2half2_rn(v.x, v.y);
        __half2 b = __floats2half2_rn(v.z, v.w);
        ((uint2*)g_xh)[i] = make_uint2(*(uint32_t*)&a, *(uint32_t*)&b);
    } else if (blk < PREP_TBLK) {
        int t = blk - PREP_XBLK;
        const float* W = (t < 1024) ? Wq : Wv;
        __half* th = g_wth + (size_t)(t < 1024 ? 0 : 1) * DIM * DIM;
        int tile = t & 1023;
        int bx = (tile & 31) * 32, by = (tile >> 5) * 32;
        __shared__ float ts[32][33];
        int xI = tid & 31, y0 = tid >> 5;
#pragma unroll
        for (int j = 0; j < 32; j += 8)
            ts[y0 + j][xI] = W[(size_t)(by + y0 + j) * DIM + bx + xI];
        __syncthreads();
#pragma unroll
        for (int j = 0; j < 32; j += 8) {
            size_t o = (size_t)(bx + y0 + j) * DIM + by + xI;
            th[o] = __float2half_rn(ts[xI][y0 + j]);
        }
    } else {
        int i = (blk - PREP_TBLK) * 256 + tid;    // 0 .. 262,143
        if (i < DIM) g_bqv[i] = bq[i];
        else if (i < 2 * DIM) g_bqv[i] = bv[i - DIM];
        if (i < BATCH * DIM) g_qsum[i] = 0.f;
        g_ctx[i] = 0.f;
    }
}

// ---------------- single-pass fp16 mma.sync GEMM -----------------------------
// CTA 256x128, 512 thr, warp tile 32x64 (16 warps: 8m x 2n), K-tile 64, 4 stages.
#define NITER 16
#define STG_BYTES 49152   // 32KB A + 16KB B

__global__ __launch_bounds__(512, 1)
void gemm_mma(const __half* __restrict__ Ah, const __half* __restrict__ Bh0,
              const float* __restrict__ bias, float* __restrict__ Cout,
              __half* __restrict__ Qh, __half* __restrict__ Vh, int mode)
{
    extern __shared__ char smem_raw[];
    const uint32_t sb = (smem_u32(smem_raw) + 127) & ~127u;
    float* scr = (float*)smem_raw;
    const int tid = threadIdx.x, wid = tid >> 5, lane = tid & 31;
    const int bm = blockIdx.y * 256, bn = blockIdx.x * 128;
    const int wm = (wid >> 1) * 32;
    const int wn = (wid & 1) * 64;

    const __half* Bh = Bh0;
    if (mode == 1) Bh += (size_t)(blockIdx.y >> 4) * DIM * DIM;
    const bool isq = (mode == 0) && (bn < 1024);
    const int cbn = (mode == 0 && bn >= 1024) ? bn - 1024 : bn;

    const int arow = tid >> 1, aci = (tid & 1) * 4;
    const int brow = tid >> 2, bci = (tid & 3) * 2;

    auto load = [&](int it) {
        const int k0 = it << 6;
        const __half* A = Ah + (size_t)(bm + arow) * DIM + k0 + aci * 8;
        const __half* B = Bh + (size_t)(bn + brow) * DIM + k0 + bci * 8;
        const uint32_t base = sb + (uint32_t)(it & 3) * STG_BYTES;
#pragma unroll
        for (int i = 0; i < 4; i++)
            cp16(base + SWZ((uint32_t)(arow * 128 + (aci + i) * 16)), A + i * 8);
#pragma unroll
        for (int i = 0; i < 2; i++)
            cp16(base + 32768 + SWZ((uint32_t)(brow * 128 + (bci + i) * 16)), B + i * 8);
        asm volatile("cp.async.commit_group;" ::: "memory");
    };

    float acc[2][8][4];
#pragma unroll
    for (int mb = 0; mb < 2; mb++)
#pragma unroll
        for (int nb = 0; nb < 8; nb++)
#pragma unroll
            for (int j = 0; j < 4; j++) acc[mb][nb][j] = 0.f;

    load(0); load(1); load(2);

    const int la_row = lane & 15;
    const int la_kh = lane >> 4;
    const int lb_n = ((lane >> 4) << 3) + (lane & 7);
    const int lb_kh = (lane >> 3) & 1;

    for (int it = 0; it < NITER; it++) {
        asm volatile("cp.async.wait_group 2;" ::: "memory");
        __syncthreads();
        if (it + 3 < NITER) load(it + 3);
        else asm volatile("cp.async.commit_group;" ::: "memory");

        const uint32_t abase = sb + (uint32_t)(it & 3) * STG_BYTES;
        const uint32_t bbase = abase + 32768;
#pragma unroll
        for (int kk = 0; kk < 4; kk++) {
            uint32_t af[2][4];
#pragma unroll
            for (int mb = 0; mb < 2; mb++) {
                uint32_t off = (uint32_t)((wm + mb * 16 + la_row) * 128 +
                                          (kk * 16 + la_kh * 8) * 2);
                ldsm4(abase + SWZ(off), af[mb][0], af[mb][1], af[mb][2], af[mb][3]);
            }
            const uint32_t boff_n = (uint32_t)((wn + lb_n) * 128 +
                                               (kk * 16 + lb_kh * 8) * 2);
            uint32_t bf[8][2];
#pragma unroll
            for (int nb2 = 0; nb2 < 4; nb2++) {
                uint32_t r0, r1, r2, r3;
                ldsm4(bbase + SWZ(boff_n + (uint32_t)(nb2 * 16 * 128)), r0, r1, r2, r3);
                bf[nb2 * 2][0] = r0;     bf[nb2 * 2][1] = r1;
                bf[nb2 * 2 + 1][0] = r2; bf[nb2 * 2 + 1][1] = r3;
            }
#pragma unroll
            for (int mb = 0; mb < 2; mb++)
#pragma unroll
                for (int nb = 0; nb < 8; nb++)
                    mma16816(acc[mb][nb], af[mb], bf[nb]);
        }
    }

    // ---- epilogue ----
    __syncthreads();
    if (tid < 128) scr[tid] = 0.f;
    __syncthreads();

    const int quad = lane >> 2, qt = lane & 3;
    float bia[8][2];
#pragma unroll
    for (int nb = 0; nb < 8; nb++) {
        int col = bn + wn + nb * 8 + qt * 2;
        bia[nb][0] = bias[col];
        bia[nb][1] = bias[col + 1];
    }
#pragma unroll
    for (int mb = 0; mb < 2; mb++) {
#pragma unroll
        for (int h = 0; h < 2; h++) {
            float v[16];
#pragma unroll
            for (int nb = 0; nb < 8; nb++) {
                v[nb * 2]     = acc[mb][nb][h * 2]     + bia[nb][0];
                v[nb * 2 + 1] = acc[mb][nb][h * 2 + 1] + bia[nb][1];
            }
            int row = bm + wm + mb * 16 + h * 8 + quad;
            if (mode == 1) {
                float* crow = Cout + (size_t)row * DIM + cbn + wn + qt * 2;
#pragma unroll
                for (int nb = 0; nb < 8; nb++)
                    *(float2*)&crow[nb * 8] = make_float2(v[nb * 2], v[nb * 2 + 1]);
            } else if (isq) {
                float m = v[0];
#pragma unroll
                for (int j = 1; j < 16; j++) m = fmaxf(m, v[j]);
                m = fmaxf(m, __shfl_xor_sync(0xffffffffu, m, 1));
                m = fmaxf(m, __shfl_xor_sync(0xffffffffu, m, 2));
                float s = 0.f;
#pragma unroll
                for (int j = 0; j < 16; j++) { v[j] = expf(v[j] - m); s += v[j]; }
                s += __shfl_xor_sync(0xffffffffu, s, 1);
                s += __shfl_xor_sync(0xffffffffu, s, 2);
                float inv = SCALE / s;
#pragma unroll
                for (int j = 0; j < 16; j++) v[j] *= inv;
                // column sums of exp(q); q in [0, SCALE] -> exp bounded, no max pass
                float es[16];
#pragma unroll
                for (int j = 0; j < 16; j++) es[j] = expf(v[j]);
#pragma unroll
                for (int off = 4; off < 32; off <<= 1)
#pragma unroll
                    for (int j = 0; j < 16; j++)
                        es[j] += __shfl_xor_sync(0xffffffffu, es[j], off);
                if (quad == 0) {
#pragma unroll
                    for (int j = 0; j < 16; j++)
                        atomicAdd(&scr[wn + (j >> 1) * 8 + qt * 2 + (j & 1)], es[j]);
                }
                __half* qrow = Qh + (size_t)row * DIM + cbn + wn + qt * 2;
#pragma unroll
                for (int nb = 0; nb < 8; nb++)
                    *(__half2*)&qrow[nb * 8] = __floats2half2_rn(v[nb * 2], v[nb * 2 + 1]);
            } else {
                __half* vrow = Vh + (size_t)row * DIM + cbn + wn + qt * 2;
#pragma unroll
                for (int nb = 0; nb < 8; nb++)
                    *(__half2*)&vrow[nb * 8] = __floats2half2_rn(v[nb * 2], v[nb * 2 + 1]);
            }
        }
    }
    if (isq) {
        __syncthreads();
        if (tid < 128) {
            int b = blockIdx.y >> 4;
            atomicAdd(&g_qsum[b * DIM + bn + tid], scr[tid]);
        }
    }
}

// ---------------- tensor-core ctx: ctx[b,h,d,e] = cinv[d]*sum_n exp(q)[n,d]*v[n,e]
__global__ __launch_bounds__(256)
void ctx_mma()
{
    __shared__ __align__(128) __half ks[64 * 64];
    __shared__ __align__(128) __half vs[64 * 64];
    const int tid = threadIdx.x, wid = tid >> 5, lane = tid & 31;
    const int bh = blockIdx.y, b = bh >> 4, h = bh & 15;
    const size_t nbase = (size_t)b * SEQ + blockIdx.x * 512;
    const __half* qb = g_qh + nbase * DIM + h * DHEAD;
    const __half* vb = g_vh + nbase * DIM + h * DHEAD;
    const uint32_t ksb = smem_u32(ks), vsb = smem_u32(vs);

    const int dslice = wid & 3;
    const int nh = wid >> 2;
    const int la_row = lane & 15;
    const int la_kh = lane >> 4;
    const int lb_n = ((lane >> 4) << 3) + (lane & 7);
    const int lb_kh = (lane >> 3) & 1;

    float acc[8][4];
#pragma unroll
    for (int nb = 0; nb < 8; nb++)
#pragma unroll
        for (int j = 0; j < 4; j++) acc[nb][j] = 0.f;

    const int r = tid >> 2;
    const int c0 = (tid & 3) * 16;

    for (int t = 0; t < 8; t++) {
        const __half* qrow = qb + (size_t)(t * 64 + r) * DIM;
        const __half* vrow = vb + (size_t)(t * 64 + r) * DIM;
        uint4 qa = *(const uint4*)(qrow + c0);
        uint4 qc = *(const uint4*)(qrow + c0 + 8);
        uint4 va = *(const uint4*)(vrow + c0);
        uint4 vc = *(const uint4*)(vrow + c0 + 8);
        __syncthreads();
        {
            const __half2* qp = (const __half2*)&qa;
#pragma unroll
            for (int j = 0; j < 4; j++) {
                __half2 e = h2exp(qp[j]);
                *(__half*)((char*)ks + SWZ((uint32_t)((c0 + 2*j) * 128 + r * 2))) =
                    __low2half(e);
                *(__half*)((char*)ks + SWZ((uint32_t)((c0 + 2*j + 1) * 128 + r * 2))) =
                    __high2half(e);
            }
            const __half2* qp2 = (const __half2*)&qc;
#pragma unroll
            for (int j = 0; j < 4; j++) {
                __half2 e = h2exp(qp2[j]);
                *(__half*)((char*)ks + SWZ((uint32_t)((c0 + 8 + 2*j) * 128 + r * 2))) =
                    __low2half(e);
                *(__half*)((char*)ks + SWZ((uint32_t)((c0 + 8 + 2*j + 1) * 128 + r * 2))) =
                    __high2half(e);
            }
            const __half* vp = (const __half*)&va;
#pragma unroll
            for (int j = 0; j < 8; j++)
                *(__half*)((char*)vs + SWZ((uint32_t)((c0 + j) * 128 + r * 2))) = vp[j];
            const __half* vp2 = (const __half*)&vc;
#pragma unroll
            for (int j = 0; j < 8; j++)
                *(__half*)((char*)vs + SWZ((uint32_t)((c0 + 8 + j) * 128 + r * 2))) = vp2[j];
        }
        __syncthreads();

#pragma unroll
        for (int s = 0; s < 2; s++) {
            const int kk = nh * 2 + s;
            uint32_t af[4];
            {
                uint32_t off = (uint32_t)((dslice * 16 + la_row) * 128 +
                                          (kk * 16 + la_kh * 8) * 2);
                ldsm4(ksb + SWZ(off), af[0], af[1], af[2], af[3]);
            }
            uint32_t bf[8][2];
#pragma unroll
            for (int eb = 0; eb < 4; eb++) {
                uint32_t off = (uint32_t)((eb * 16 + lb_n) * 128 +
                                          (kk * 16 + lb_kh * 8) * 2);
                uint32_t r0, r1, r2, r3;
                ldsm4(vsb + SWZ(off), r0, r1, r2, r3);
                bf[eb * 2][0] = r0;     bf[eb * 2][1] = r1;
                bf[eb * 2 + 1][0] = r2; bf[eb * 2 + 1][1] = r3;
            }
#pragma unroll
            for (int nb = 0; nb < 8; nb++)
                mma16816(acc[nb], af, bf[nb]);
        }
    }

    // reduce with inline cinv[d] = SCALE / qsum
    const int g = lane >> 2, t4 = lane & 3;
    const int d0 = dslice * 16 + g;
    const float ci0 = SCALE / g_qsum[b * DIM + h * DHEAD + d0];
    const float ci1 = SCALE / g_qsum[b * DIM + h * DHEAD + d0 + 8];
    float* cb = g_ctx + (size_t)bh * 4096;
#pragma unroll
    for (int nb = 0; nb < 8; nb++) {
        int e = nb * 8 + t4 * 2;
        atomicAdd(&cb[d0 * 64 + e],           acc[nb][0] * ci0);
        atomicAdd(&cb[d0 * 64 + e + 1],       acc[nb][1] * ci0);
        atomicAdd(&cb[(d0 + 8) * 64 + e],     acc[nb][2] * ci1);
        atomicAdd(&cb[(d0 + 8) * 64 + e + 1], acc[nb][3] * ci1);
    }
}

// ---------------- tensor-core fold: Wfold^T[b][jt+j][h*64+d] -----------------
//   = sum_e Wo[h*64+e][jt+j] * ctx[b,h,d,e]
// R15 staging restored: 32 independent scalar loads/stores per thread (high MLP).
__global__ __launch_bounds__(256)
void fold_mma(const float* __restrict__ Wo, __half* __restrict__ fh)
{
    __shared__ __align__(128) __half aw[128 * 64];  // [j][e] SWZ
    __shared__ __align__(128) __half cs[64 * 64];   // [d][e] SWZ
    const int tid = threadIdx.x, wid = tid >> 5, lane = tid & 31;
    const int bh = blockIdx.y, b = bh >> 4, h = bh & 15;
    const int jt = blockIdx.x * 128;
    const uint32_t awb = smem_u32(aw), csb = smem_u32(cs);

    // ctx -> cs fp16 (vectorized, conflict-free)
    const float* cb = g_ctx + (size_t)bh * 4096;
    for (int i = tid; i < 2048; i += 256) {
        int d = i >> 5, e2 = (i & 31) * 2;
        float2 f = *(const float2*)&cb[d * 64 + e2];
        *(__half2*)((char*)cs + SWZ((uint32_t)(d * 128 + e2 * 2))) =
            __floats2half2_rn(f.x, f.y);
    }
    // Wo -> aw transposed fp16 (coalesced gmem read, scalar swizzled store)
    const float* wo = Wo + (size_t)(h * 64) * DIM + jt;
    for (int i = tid; i < 8192; i += 256) {
        int e = i >> 7, j = i & 127;
        *(__half*)((char*)aw + SWZ((uint32_t)(j * 128 + e * 2))) =
            __float2half_rn(wo[(size_t)e * DIM + j]);
    }
    __syncthreads();

    const int la_row = lane & 15, la_kh = lane >> 4;
    const int lb_n = ((lane >> 4) << 3) + (lane & 7);
    const int lb_kh = (lane >> 3) & 1;
    const int j0 = wid * 16;

    float acc[8][4];
#pragma unroll
    for (int nb = 0; nb < 8; nb++)
#pragma unroll
        for (int j = 0; j < 4; j++) acc[nb][j] = 0.f;

#pragma unroll
    for (int kk = 0; kk < 4; kk++) {
        uint32_t af[4];
        ldsm4(awb + SWZ((uint32_t)((j0 + la_row) * 128 + (kk * 16 + la_kh * 8) * 2)),
              af[0], af[1], af[2], af[3]);
        uint32_t bf[8][2];
#pragma unroll
        for (int nb2 = 0; nb2 < 4; nb2++) {
            uint32_t r0, r1, r2, r3;
            ldsm4(csb + SWZ((uint32_t)((nb2 * 16 + lb_n) * 128 +
                                       (kk * 16 + lb_kh * 8) * 2)), r0, r1, r2, r3);
            bf[nb2 * 2][0] = r0;     bf[nb2 * 2][1] = r1;
            bf[nb2 * 2 + 1][0] = r2; bf[nb2 * 2 + 1][1] = r3;
        }
#pragma unroll
        for (int nb = 0; nb < 8; nb++)
            mma16816(acc[nb], af, bf[nb]);
    }

    // store fp16: fh[(b*DIM + jt + j)*DIM + h*64 + d]
    const int quad = lane >> 2, qt = lane & 3;
#pragma unroll
    for (int h8 = 0; h8 < 2; h8++) {
        int j = j0 + h8 * 8 + quad;
        __half* frow = fh + ((size_t)(b * DIM) + jt + j) * DIM + h * 64 + qt * 2;
#pragma unroll
        for (int nb = 0; nb < 8; nb++)
            *(__half2*)&frow[nb * 8] =
                __floats2half2_rn(acc[nb][h8 * 2], acc[nb][h8 * 2 + 1]);
    }
}

// -----------------------------------------------------------------------------
extern "C" void kernel_launch(void* const* d_in, const int* in_sizes, int n_in,
                              void* d_out, int out_size)
{
    const float* x  = (const float*)d_in[0];
    const float* Wq = (const float*)d_in[1];
    const float* bq = (const float*)d_in[2];
    const float* Wv = (const float*)d_in[5];
    const float* bv = (const float*)d_in[6];
    const float* Wo = (const float*)d_in[7];
    const float* bo = (const float*)d_in[8];
    float* out = (float*)d_out;

    __half *xh, *qh, *vh, *wth, *foldh;
    float* bqv;
    cudaGetSymbolAddress((void**)&bqv, g_bqv);
    cudaGetSymbolAddress((void**)&xh, g_xh);
    cudaGetSymbolAddress((void**)&qh, g_qh);
    cudaGetSymbolAddress((void**)&vh, g_vh);
    cudaGetSymbolAddress((void**)&wth, g_wth);
    cudaGetSymbolAddress((void**)&foldh, g_foldh);

    const int SMEM = 4 * STG_BYTES + 256;   // ~192.25KB (cap 227KB)
    cudaFuncSetAttribute(gemm_mma, cudaFuncAttributeMaxDynamicSharedMemorySize, SMEM);

    prep<<<PREP_NBLK, 256>>>((const float4*)x, Wq, Wv, bq, bv);

    // fused QV GEMM: N = 2048, M-tiles of 256
    gemm_mma<<<dim3(2 * DIM / 128, MROWS / 256), 512, SMEM>>>(
        xh, wth, bqv, nullptr, qh, vh, 0);
    ctx_mma<<<dim3(8, BATCH * HEADS), 256>>>();
    fold_mma<<<dim3(DIM / 128, BATCH * HEADS), 256>>>(Wo, foldh);
    // O GEMM: out = qh @ Wfold[b]^T + bo
    gemm_mma<<<dim3(DIM / 128, MROWS / 256), 512, SMEM>>>(
        qh, foldh, bo, out, nullptr, nullptr, 1);
}